// round 14
// baseline (speedup 1.0000x reference)
#include <cuda_runtime.h>
#include <cuda_bf16.h>
#include <cstdint>

#define NTHREADS 224                 // 7 warps
#define NWARPS (NTHREADS / 32)
#define GPS 224                      // groups per stage (== NTHREADS)
#define CTAS_PER_SM 4
#define NBLOCKS (148 * CTAS_PER_SM)  // 592: single wave at 4 CTAs/SM

// smem: two 28KB stage buffers + 2 mbarriers
#define BYTES_L   (GPS * 48)
#define BYTES_S   (GPS * 48)
#define BYTES_H   (GPS * 16)
#define BYTES_C   (GPS * 16)
#define BUF_BYTES (BYTES_L + BYTES_S + BYTES_H + BYTES_C)   // 28672
#define OFF_L 0
#define OFF_S (OFF_L + BYTES_L)
#define OFF_H (OFF_S + BYTES_S)
#define OFF_C (OFF_H + BYTES_H)
#define SMEM_MBAR (2 * BUF_BYTES)
#define SMEM_TOTAL (SMEM_MBAR + 16)

__device__ float g_partials[NBLOCKS];
__device__ int   g_ticket = 0;

__device__ __forceinline__ float ex2f(float x) {
    float y; asm("ex2.approx.ftz.f32 %0, %1;" : "=f"(y) : "f"(x)); return y;
}
__device__ __forceinline__ float lg2f(float x) {
    float y; asm("lg2.approx.ftz.f32 %0, %1;" : "=f"(y) : "f"(x)); return y;
}
__device__ __forceinline__ float rcpf(float x) {
    float y; asm("rcp.approx.ftz.f32 %0, %1;" : "=f"(y) : "f"(x)); return y;
}
__device__ __forceinline__ uint32_t s2u(const void* p) {
    return (uint32_t)__cvta_generic_to_shared(p);
}
__device__ __forceinline__ void mbar_init(uint32_t mbar, uint32_t cnt) {
    asm volatile("mbarrier.init.shared.b64 [%0], %1;" :: "r"(mbar), "r"(cnt) : "memory");
}
__device__ __forceinline__ void mbar_expect_tx(uint32_t mbar, uint32_t bytes) {
    asm volatile("mbarrier.arrive.expect_tx.shared.b64 _, [%0], %1;"
                 :: "r"(mbar), "r"(bytes) : "memory");
}
__device__ __forceinline__ void bulk_g2s(uint32_t dst, const void* src,
                                         uint32_t bytes, uint32_t mbar) {
    asm volatile("cp.async.bulk.shared::cta.global.mbarrier::complete_tx::bytes "
                 "[%0], [%1], %2, [%3];"
                 :: "r"(dst), "l"(src), "r"(bytes), "r"(mbar) : "memory");
}
__device__ __forceinline__ void mbar_wait(uint32_t mbar, uint32_t parity) {
    uint32_t done;
    asm volatile(
        "{\n\t.reg .pred p;\n\t"
        "mbarrier.try_wait.parity.acquire.cta.shared::cta.b64 p, [%1], %2;\n\t"
        "selp.b32 %0, 1, 0, p;\n\t}"
        : "=r"(done) : "r"(mbar), "r"(parity) : "memory");
    if (!done) {
        asm volatile(
            "{\n\t.reg .pred P1;\n\t"
            "WAIT_LOOP_%=:\n\t"
            "mbarrier.try_wait.parity.acquire.cta.shared::cta.b64 P1, [%0], %1, 0x989680;\n\t"
            "@P1 bra.uni WAIT_DONE_%=;\n\t"
            "bra.uni WAIT_LOOP_%=;\n\t"
            "WAIT_DONE_%=:\n\t}"
            :: "r"(mbar), "r"(parity) : "memory");
    }
}

// loss contribution: accL (log2 domain), accR (linear); total = 0.5*(ln2*accL - accR)
__device__ __forceinline__ void sample_acc(float l0, float l1, float l2,
                                           float t0, float t1, float t2,
                                           int h, float conf,
                                           float& accL, float& accR) {
    const float L2E = 1.44269504088896f;
    float low_inv = fmaxf(rcpf(__fmaf_rn(-2.0f, conf, 3.7f)), 0.33333334f);
    float invT = (conf > 0.9f) ? 0.66666667f : ((conf > 0.6f) ? 0.5f : low_inv);

    float a = invT * L2E;
    float p = ex2f(l0 * a) + ex2f(l1 * a) + ex2f(l2 * a);        // KL lse (log2)
    float q = ex2f(l0 * L2E) + ex2f(l1 * L2E) + ex2f(l2 * L2E);  // CE lse (log2)
    float tl = t0 * lg2f(t0);
    tl = __fmaf_rn(t1, lg2f(t1), tl);
    tl = __fmaf_rn(t2, lg2f(t2), tl);
    float td = t0 * l0;
    td = __fmaf_rn(t1, l1, td);
    td = __fmaf_rn(t2, l2, td);
    float lh = (h == 0) ? l0 : ((h == 1) ? l1 : l2);

    accL += lg2f(p * q) + tl;
    accR += __fmaf_rn(invT, td, lh);
}

__global__ void __launch_bounds__(NTHREADS, CTAS_PER_SM)
adl_bulk_kernel(const char* __restrict__ logits_c,
                const char* __restrict__ hard_c,
                const char* __restrict__ soft_c,
                const char* __restrict__ conf_c,
                int ngroups, float* __restrict__ out, float inv_n) {
    extern __shared__ char smem[];
    const uint32_t smem_u = s2u(smem);
    const int tid = threadIdx.x;
    const int lane = tid & 31;
    const int warp = tid >> 5;

    // contiguous per-CTA chunk [chunk_lo, chunk_hi)
    const int chunk_sz = (ngroups + NBLOCKS - 1) / NBLOCKS;
    const int chunk_lo = blockIdx.x * chunk_sz;
    const int chunk_hi = min(chunk_lo + chunk_sz, ngroups);
    const int nstages  = (chunk_hi > chunk_lo)
                       ? (chunk_hi - chunk_lo + GPS - 1) / GPS : 0;

    if (tid == 0) {
        mbar_init(smem_u + SMEM_MBAR, 1);
        mbar_init(smem_u + SMEM_MBAR + 8, 1);
    }
    __syncthreads();

    auto prefetch = [&](int st, int b) {
        const int gbase = chunk_lo + st * GPS;
        const int cnt = min(GPS, chunk_hi - gbase);
        const uint32_t bl = (uint32_t)cnt * 48;
        const uint32_t bh = (uint32_t)cnt * 16;
        const uint32_t mbar = smem_u + SMEM_MBAR + b * 8;
        const uint32_t base = smem_u + b * BUF_BYTES;
        mbar_expect_tx(mbar, 2 * bl + 2 * bh);
        bulk_g2s(base + OFF_L, logits_c + (size_t)gbase * 48, bl, mbar);
        bulk_g2s(base + OFF_S, soft_c   + (size_t)gbase * 48, bl, mbar);
        bulk_g2s(base + OFF_H, hard_c   + (size_t)gbase * 16, bh, mbar);
        bulk_g2s(base + OFF_C, conf_c   + (size_t)gbase * 16, bh, mbar);
    };

    float accL = 0.0f, accR = 0.0f;
    if (tid == 0 && nstages > 0) prefetch(0, 0);

    for (int i = 0; i < nstages; ++i) {
        const int b = i & 1;
        if (tid == 0 && i + 1 < nstages) prefetch(i + 1, (i + 1) & 1);

        mbar_wait(smem_u + SMEM_MBAR + b * 8, (i >> 1) & 1);

        const int cnt = min(GPS, chunk_hi - (chunk_lo + i * GPS));
        if (tid < cnt) {
            const char* base = smem + b * BUF_BYTES;
            const float4* Lp = (const float4*)(base + OFF_L) + tid * 3;
            const float4* Sp = (const float4*)(base + OFF_S) + tid * 3;
            const float4 L0 = Lp[0], L1 = Lp[1], L2 = Lp[2];
            const float4 S0 = Sp[0], S1 = Sp[1], S2 = Sp[2];
            const int4   H  = ((const int4*)(base + OFF_H))[tid];
            const float4 Cf = ((const float4*)(base + OFF_C))[tid];

            sample_acc(L0.x, L0.y, L0.z, S0.x, S0.y, S0.z, H.x, Cf.x, accL, accR);
            sample_acc(L0.w, L1.x, L1.y, S0.w, S1.x, S1.y, H.y, Cf.y, accL, accR);
            sample_acc(L1.z, L1.w, L2.x, S1.z, S1.w, S2.x, H.z, Cf.z, accL, accR);
            sample_acc(L2.y, L2.z, L2.w, S2.y, S2.z, S2.w, H.w, Cf.w, accL, accR);
        }
        __syncthreads();   // buffer b free for reuse
    }

    float acc = 0.5f * (0.69314718055995f * accL - accR);

    __shared__ float warp_sums[NWARPS];
    #pragma unroll
    for (int off = 16; off > 0; off >>= 1)
        acc += __shfl_down_sync(0xFFFFFFFFu, acc, off);
    if (lane == 0) warp_sums[warp] = acc;
    __syncthreads();

    __shared__ bool is_last;
    if (tid == 0) {
        float v = 0.0f;
        #pragma unroll
        for (int w = 0; w < NWARPS; w++) v += warp_sums[w];
        g_partials[blockIdx.x] = v;
        __threadfence();
        int t = atomicAdd(&g_ticket, 1);
        is_last = (t == NBLOCKS - 1);
    }
    __syncthreads();

    if (is_last) {
        __threadfence();
        const volatile float* vp = g_partials;
        float facc = 0.0f;
        for (int j = tid; j < NBLOCKS; j += NTHREADS)
            facc += vp[j];
        #pragma unroll
        for (int off = 16; off > 0; off >>= 1)
            facc += __shfl_down_sync(0xFFFFFFFFu, facc, off);
        if (lane == 0) warp_sums[warp] = facc;
        __syncthreads();
        if (tid == 0) {
            float s = 0.0f;
            #pragma unroll
            for (int w = 0; w < NWARPS; w++) s += warp_sums[w];
            out[0] = s * inv_n;
            g_ticket = 0;
        }
    }
}

extern "C" void kernel_launch(void* const* d_in, const int* in_sizes, int n_in,
                              void* d_out, int out_size) {
    // metadata order: logits (B*3 f32), hard_labels (B i32), soft_labels (B*3 f32), confidences (B f32)
    static bool attr_set = false;
    if (!attr_set) {
        cudaFuncSetAttribute(adl_bulk_kernel,
                             cudaFuncAttributeMaxDynamicSharedMemorySize, SMEM_TOTAL);
        attr_set = true;
    }
    const int n = in_sizes[1];          // B
    const int ngroups = n / 4;

    adl_bulk_kernel<<<NBLOCKS, NTHREADS, SMEM_TOTAL>>>(
        (const char*)d_in[0], (const char*)d_in[1],
        (const char*)d_in[2], (const char*)d_in[3],
        ngroups, (float*)d_out, 1.0f / (float)n);
}

// round 17
// speedup vs baseline: 1.1752x; 1.1752x over previous
#include <cuda_runtime.h>
#include <cuda_bf16.h>
#include <cstdint>

#define NTHREADS 256
#define NWARPS (NTHREADS / 32)
#define GPS 256                      // groups per stage (== NTHREADS)
#define NBLOCKS (148 * 3)            // 444: single wave at 3 CTAs/SM (validated R13)

// smem: two 32KB stage buffers + 2 mbarriers
#define BYTES_L   (GPS * 48)
#define BYTES_S   (GPS * 48)
#define BYTES_H   (GPS * 16)
#define BYTES_C   (GPS * 16)
#define BUF_BYTES (BYTES_L + BYTES_S + BYTES_H + BYTES_C)   // 32768
#define OFF_L 0
#define OFF_S (OFF_L + BYTES_L)
#define OFF_H (OFF_S + BYTES_S)
#define OFF_C (OFF_H + BYTES_H)
#define SMEM_MBAR (2 * BUF_BYTES)
#define SMEM_TOTAL (SMEM_MBAR + 16)

__device__ float g_partials[NBLOCKS];
__device__ int   g_ticket = 0;

__device__ __forceinline__ float ex2f(float x) {
    float y; asm("ex2.approx.ftz.f32 %0, %1;" : "=f"(y) : "f"(x)); return y;
}
__device__ __forceinline__ float lg2f(float x) {
    float y; asm("lg2.approx.ftz.f32 %0, %1;" : "=f"(y) : "f"(x)); return y;
}
__device__ __forceinline__ float rcpf(float x) {
    float y; asm("rcp.approx.ftz.f32 %0, %1;" : "=f"(y) : "f"(x)); return y;
}
__device__ __forceinline__ uint32_t s2u(const void* p) {
    return (uint32_t)__cvta_generic_to_shared(p);
}
__device__ __forceinline__ void mbar_init(uint32_t mbar, uint32_t cnt) {
    asm volatile("mbarrier.init.shared.b64 [%0], %1;" :: "r"(mbar), "r"(cnt) : "memory");
}
__device__ __forceinline__ void mbar_expect_tx(uint32_t mbar, uint32_t bytes) {
    asm volatile("mbarrier.arrive.expect_tx.shared.b64 _, [%0], %1;"
                 :: "r"(mbar), "r"(bytes) : "memory");
}
__device__ __forceinline__ void bulk_g2s(uint32_t dst, const void* src,
                                         uint32_t bytes, uint32_t mbar) {
    asm volatile("cp.async.bulk.shared::cta.global.mbarrier::complete_tx::bytes "
                 "[%0], [%1], %2, [%3];"
                 :: "r"(dst), "l"(src), "r"(bytes), "r"(mbar) : "memory");
}
__device__ __forceinline__ void mbar_wait(uint32_t mbar, uint32_t parity) {
    uint32_t done;
    asm volatile(
        "{\n\t.reg .pred p;\n\t"
        "mbarrier.try_wait.parity.acquire.cta.shared::cta.b64 p, [%1], %2;\n\t"
        "selp.b32 %0, 1, 0, p;\n\t}"
        : "=r"(done) : "r"(mbar), "r"(parity) : "memory");
    if (!done) {
        asm volatile(
            "{\n\t.reg .pred P1;\n\t"
            "WAIT_LOOP_%=:\n\t"
            "mbarrier.try_wait.parity.acquire.cta.shared::cta.b64 P1, [%0], %1, 0x989680;\n\t"
            "@P1 bra.uni WAIT_DONE_%=;\n\t"
            "bra.uni WAIT_LOOP_%=;\n\t"
            "WAIT_DONE_%=:\n\t}"
            :: "r"(mbar), "r"(parity) : "memory");
    }
}

// loss contribution: accL (log2 domain), accR (linear); total = 0.5*(ln2*accL - accR)
__device__ __forceinline__ void sample_acc(float l0, float l1, float l2,
                                           float t0, float t1, float t2,
                                           int h, float conf,
                                           float& accL, float& accR) {
    const float L2E = 1.44269504088896f;
    float low_inv = fmaxf(rcpf(__fmaf_rn(-2.0f, conf, 3.7f)), 0.33333334f);
    float invT = (conf > 0.9f) ? 0.66666667f : ((conf > 0.6f) ? 0.5f : low_inv);

    float a = invT * L2E;
    float p = ex2f(l0 * a) + ex2f(l1 * a) + ex2f(l2 * a);        // KL lse (log2)
    float q = ex2f(l0 * L2E) + ex2f(l1 * L2E) + ex2f(l2 * L2E);  // CE lse (log2)
    float tl = t0 * lg2f(t0);
    tl = __fmaf_rn(t1, lg2f(t1), tl);
    tl = __fmaf_rn(t2, lg2f(t2), tl);
    float td = t0 * l0;
    td = __fmaf_rn(t1, l1, td);
    td = __fmaf_rn(t2, l2, td);
    float lh = (h == 0) ? l0 : ((h == 1) ? l1 : l2);

    accL += lg2f(p * q) + tl;
    accR += __fmaf_rn(invT, td, lh);
}

__global__ void __launch_bounds__(NTHREADS, 3)
adl_bulk_kernel(const char* __restrict__ logits_c,
                const char* __restrict__ hard_c,
                const char* __restrict__ soft_c,
                const char* __restrict__ conf_c,
                int ngroups, float* __restrict__ out, float inv_n) {
    extern __shared__ char smem[];
    const uint32_t smem_u = s2u(smem);
    const int tid = threadIdx.x;
    const int lane = tid & 31;
    const int warp = tid >> 5;

    // contiguous per-CTA chunk [chunk_lo, chunk_hi): sequential streaming
    const int chunk_sz = (ngroups + NBLOCKS - 1) / NBLOCKS;
    const int chunk_lo = min(blockIdx.x * chunk_sz, ngroups);
    const int chunk_hi = min(chunk_lo + chunk_sz, ngroups);
    const int nstages  = (chunk_hi - chunk_lo + GPS - 1) / GPS;

    if (tid == 0) {
        mbar_init(smem_u + SMEM_MBAR, 1);
        mbar_init(smem_u + SMEM_MBAR + 8, 1);
    }
    __syncthreads();

    auto prefetch = [&](int st, int b) {
        const int gbase = chunk_lo + st * GPS;
        const int cnt = min(GPS, chunk_hi - gbase);
        const uint32_t bl = (uint32_t)cnt * 48;
        const uint32_t bh = (uint32_t)cnt * 16;
        const uint32_t mbar = smem_u + SMEM_MBAR + b * 8;
        const uint32_t base = smem_u + b * BUF_BYTES;
        mbar_expect_tx(mbar, 2 * bl + 2 * bh);
        bulk_g2s(base + OFF_L, logits_c + (size_t)gbase * 48, bl, mbar);
        bulk_g2s(base + OFF_S, soft_c   + (size_t)gbase * 48, bl, mbar);
        bulk_g2s(base + OFF_H, hard_c   + (size_t)gbase * 16, bh, mbar);
        bulk_g2s(base + OFF_C, conf_c   + (size_t)gbase * 16, bh, mbar);
    };

    float accL = 0.0f, accR = 0.0f;
    if (tid == 0 && nstages > 0) prefetch(0, 0);

    for (int i = 0; i < nstages; ++i) {
        const int b = i & 1;
        if (tid == 0 && i + 1 < nstages) prefetch(i + 1, (i + 1) & 1);

        mbar_wait(smem_u + SMEM_MBAR + b * 8, (i >> 1) & 1);

        const int cnt = min(GPS, chunk_hi - (chunk_lo + i * GPS));
        if (tid < cnt) {
            const char* base = smem + b * BUF_BYTES;
            const float4* Lp = (const float4*)(base + OFF_L) + tid * 3;
            const float4* Sp = (const float4*)(base + OFF_S) + tid * 3;
            const float4 L0 = Lp[0], L1 = Lp[1], L2 = Lp[2];
            const float4 S0 = Sp[0], S1 = Sp[1], S2 = Sp[2];
            const int4   H  = ((const int4*)(base + OFF_H))[tid];
            const float4 Cf = ((const float4*)(base + OFF_C))[tid];

            sample_acc(L0.x, L0.y, L0.z, S0.x, S0.y, S0.z, H.x, Cf.x, accL, accR);
            sample_acc(L0.w, L1.x, L1.y, S0.w, S1.x, S1.y, H.y, Cf.y, accL, accR);
            sample_acc(L1.z, L1.w, L2.x, S1.z, S1.w, S2.x, H.z, Cf.z, accL, accR);
            sample_acc(L2.y, L2.z, L2.w, S2.y, S2.z, S2.w, H.w, Cf.w, accL, accR);
        }
        __syncthreads();   // buffer b free for reuse
    }

    float acc = 0.5f * (0.69314718055995f * accL - accR);

    __shared__ float warp_sums[NWARPS];
    #pragma unroll
    for (int off = 16; off > 0; off >>= 1)
        acc += __shfl_down_sync(0xFFFFFFFFu, acc, off);
    if (lane == 0) warp_sums[warp] = acc;
    __syncthreads();

    __shared__ bool is_last;
    if (tid == 0) {
        float v = 0.0f;
        #pragma unroll
        for (int w = 0; w < NWARPS; w++) v += warp_sums[w];
        g_partials[blockIdx.x] = v;
        __threadfence();
        int t = atomicAdd(&g_ticket, 1);
        is_last = (t == NBLOCKS - 1);
    }
    __syncthreads();

    if (is_last) {
        __threadfence();
        const volatile float* vp = g_partials;
        float facc = 0.0f;
        for (int j = tid; j < NBLOCKS; j += NTHREADS)
            facc += vp[j];
        #pragma unroll
        for (int off = 16; off > 0; off >>= 1)
            facc += __shfl_down_sync(0xFFFFFFFFu, facc, off);
        if (lane == 0) warp_sums[warp] = facc;
        __syncthreads();
        if (tid == 0) {
            float s = 0.0f;
            #pragma unroll
            for (int w = 0; w < NWARPS; w++) s += warp_sums[w];
            out[0] = s * inv_n;
            g_ticket = 0;
        }
    }
}

extern "C" void kernel_launch(void* const* d_in, const int* in_sizes, int n_in,
                              void* d_out, int out_size) {
    // metadata order: logits (B*3 f32), hard_labels (B i32), soft_labels (B*3 f32), confidences (B f32)
    static bool attr_set = false;
    if (!attr_set) {
        cudaFuncSetAttribute(adl_bulk_kernel,
                             cudaFuncAttributeMaxDynamicSharedMemorySize, SMEM_TOTAL);
        attr_set = true;
    }
    const int n = in_sizes[1];          // B
    const int ngroups = n / 4;

    adl_bulk_kernel<<<NBLOCKS, NTHREADS, SMEM_TOTAL>>>(
        (const char*)d_in[0], (const char*)d_in[1],
        (const char*)d_in[2], (const char*)d_in[3],
        ngroups, (float*)d_out, 1.0f / (float)n);
}